// round 1
// baseline (speedup 1.0000x reference)
#include <cuda_runtime.h>

namespace {

constexpr int D  = 256;
constexpr int H  = 8;
constexpr int HD = 32;
constexpr int P  = 20;
constexpr int KA = 7;
constexpr int F  = 768;
constexpr int R  = 16;      // rows per block
constexpr int NT = 256;     // threads per block
constexpr float EPS = 1e-5f;
constexpr float NEG_BIG = -3.0e38f;

// ---- dynamic shared memory layout (float offsets) ----
constexpr int QKS = 268;    // qk row stride (12h+e mod 32 -> conflict-free)
constexpr int FS  = 257;    // feats row stride ((p+e) mod 32 -> conflict-free)
constexpr int AS  = 24;     // attn row stride

constexpr int OFF_WLIN  = 0;                       // 7*256   = 1792
constexpr int OFF_QK    = OFF_WLIN + KA * D;       // 8*268   = 2144
constexpr int OFF_QKB   = OFF_QK + H * QKS;        // 8
constexpr int OFF_ROADS = OFF_QKB + H;             // 140
constexpr int OFF_MASK  = OFF_ROADS + P * KA;      // 20 ints
constexpr int OFF_ATTN  = OFF_MASK + P;            // 8*24    = 192
constexpr int OFF_FEATS = OFF_ATTN + H * AS;       // 20*257  = 5140
constexpr int OFF_CTX   = OFF_FEATS + P * FS;      // 16*256  = 4096 (16B aligned: 9436%4==0)
constexpr int OFF_EMB   = OFF_CTX + R * D;         // 16*256  = 4096
constexpr int OFF_U     = OFF_EMB + R * D;         // union: wfeat 16*8*256 | hidden 16*768
constexpr int SMEM_FLOATS = OFF_U + R * H * D;     // 50396 floats
constexpr int SMEM_BYTES  = SMEM_FLOATS * 4;       // 201584 bytes

static_assert(OFF_CTX % 4 == 0 && OFF_EMB % 4 == 0 && OFF_U % 4 == 0, "float4 alignment");

} // namespace

// precomputed query-folded K projection
__device__ float g_qk[H * D];   // [h][e]
__device__ float g_qkb[H];

// ============================================================================
// Kernel A: fold q = (seeds@wq+bq)*scale into wk:  qk[h][e] = sum_d' qs[h,d']*wk[e,h*32+d']
// ============================================================================
__global__ void __launch_bounds__(NT, 1) precompute_qk_kernel(
    const float* __restrict__ seeds, const float* __restrict__ wq,
    const float* __restrict__ bq,    const float* __restrict__ wk,
    const float* __restrict__ bk)
{
    __shared__ float qs[D];
    const int t = threadIdx.x;

    // q[t] = sum_i seeds[i] * wq[i][t] + bq[t], then * 1/sqrt(hd)
    float acc = bq[t];
    for (int i = 0; i < D; i++) acc += seeds[i] * wq[i * D + t];
    qs[t] = acc * 0.17677669529663689f;  // 1/sqrt(32)
    __syncthreads();

    // thread t = e
    #pragma unroll
    for (int h = 0; h < H; h++) {
        float a = 0.f;
        #pragma unroll
        for (int dp = 0; dp < HD; dp++)
            a += qs[h * HD + dp] * wk[t * D + h * HD + dp];
        g_qk[h * D + t] = a;
    }
    if (t < H) {
        float a = 0.f;
        #pragma unroll
        for (int dp = 0; dp < HD; dp++)
            a += qs[t * HD + dp] * bk[t * HD + dp];
        g_qkb[t] = a;
    }
}

// ============================================================================
// Kernel B: fused encoder. grid = BNS/R blocks, 256 threads, R=16 rows/block.
// ============================================================================
__global__ void __launch_bounds__(NT, 1) fused_encoder_kernel(
    const float* __restrict__ roads,  const float* __restrict__ w_lin,
    const float* __restrict__ b_lin,  const float* __restrict__ wv,
    const float* __restrict__ bv,     const float* __restrict__ w_out,
    const float* __restrict__ b_out,  const float* __restrict__ ln1_g,
    const float* __restrict__ ln1_b,  const float* __restrict__ w1,
    const float* __restrict__ b1,     const float* __restrict__ w2,
    const float* __restrict__ b2,     const float* __restrict__ ln2_g,
    const float* __restrict__ ln2_b,  float* __restrict__ out,
    int BNS)
{
    extern __shared__ float sm[];
    int* smask = (int*)(sm + OFF_MASK);
    const int t = threadIdx.x;
    const long base_row = (long)blockIdx.x * R;

    // ---- load block-resident small tensors ----
    for (int i = t; i < KA * D; i += NT) sm[OFF_WLIN + i] = w_lin[i];
    #pragma unroll
    for (int h = 0; h < H; h++) sm[OFF_QK + h * QKS + t] = g_qk[h * D + t];
    if (t < H) sm[OFF_QKB + t] = g_qkb[t];
    __syncthreads();

    // hoist w_lin column + bias for this thread's d = t
    float wl[KA];
    #pragma unroll
    for (int a = 0; a < KA; a++) wl[a] = sm[OFF_WLIN + a * D + t];
    const float blv = b_lin[t];

    // ================= Phase 1: per-row attention prologue =================
    for (int r = 0; r < R; r++) {
        const long row = base_row + r;
        const bool valid = (row < BNS);

        // roads -> shared
        if (valid && t < P * KA) sm[OFF_ROADS + t] = roads[row * (P * KA) + t];
        __syncthreads();

        // mask: point padding iff attr-sum exactly 0
        if (t < P) {
            float s = 0.f;
            #pragma unroll
            for (int a = 0; a < KA; a++) s += sm[OFF_ROADS + t * KA + a];
            smask[t] = (s == 0.0f) ? 1 : 0;
        }
        __syncthreads();
        if (t == 0) {
            int all = 1;
            #pragma unroll
            for (int p = 0; p < P; p++) all &= smask[p];
            if (all) smask[0] = 0;   // unmask first point if fully masked
        }

        // feats[p][t] = roads[p,:] . w_lin[:,t] + b_lin[t]
        #pragma unroll
        for (int p = 0; p < P; p++) {
            float acc = blv;
            #pragma unroll
            for (int a = 0; a < KA; a++)
                acc += sm[OFF_ROADS + p * KA + a] * wl[a];
            sm[OFF_FEATS + p * FS + t] = acc;
        }
        __syncthreads();

        // scores[h][p] = feats[p,:] . qk[h,:] + qkb[h]   (160 threads)
        if (t < H * P) {
            const int h = t / P, p = t % P;
            float acc = sm[OFF_QKB + h];
            #pragma unroll 4
            for (int e = 0; e < D; e++)
                acc += sm[OFF_FEATS + p * FS + e] * sm[OFF_QK + h * QKS + e];
            if (smask[p]) acc = NEG_BIG;
            sm[OFF_ATTN + h * AS + p] = acc;
        }
        __syncthreads();

        // softmax over P per head (8 threads)
        if (t < H) {
            float mx = NEG_BIG;
            #pragma unroll
            for (int p = 0; p < P; p++) mx = fmaxf(mx, sm[OFF_ATTN + t * AS + p]);
            float ex[P]; float ssum = 0.f;
            #pragma unroll
            for (int p = 0; p < P; p++) {
                float e = __expf(sm[OFF_ATTN + t * AS + p] - mx);
                ex[p] = e; ssum += e;
            }
            const float inv = 1.f / ssum;
            #pragma unroll
            for (int p = 0; p < P; p++) sm[OFF_ATTN + t * AS + p] = ex[p] * inv;
        }
        __syncthreads();

        // wfeat[r][h][t] = sum_p attn[h][p] * feats[p][t]
        {
            float fv[P];
            #pragma unroll
            for (int p = 0; p < P; p++) fv[p] = sm[OFF_FEATS + p * FS + t];
            #pragma unroll
            for (int h = 0; h < H; h++) {
                float acc = 0.f;
                #pragma unroll
                for (int p = 0; p < P; p++)
                    acc += sm[OFF_ATTN + h * AS + p] * fv[p];
                sm[OFF_U + (r * H + h) * D + t] = acc;
            }
        }
        __syncthreads();
    }

    // ================= Phase 2a: ctx[r][t] = wfeat[r][h,:] @ wv[:,t] + bv[t] ====
    {
        const int h = t >> 5;             // warp id = head
        const float* wvp = wv + t;        // column t = h*32 + lane
        float acc[R];
        #pragma unroll
        for (int r = 0; r < R; r++) acc[r] = 0.f;

        float c0 = wvp[0*D], c1 = wvp[1*D], c2 = wvp[2*D], c3 = wvp[3*D];
        float n0 = 0.f, n1 = 0.f, n2 = 0.f, n3 = 0.f;
        #pragma unroll 1
        for (int e = 0; e < D; e += 4) {
            if (e + 4 < D) {
                n0 = wvp[(e+4)*D]; n1 = wvp[(e+5)*D];
                n2 = wvp[(e+6)*D]; n3 = wvp[(e+7)*D];
            }
            #pragma unroll
            for (int r = 0; r < R; r++) {
                float4 wf = *(const float4*)&sm[OFF_U + (r * H + h) * D + e];
                acc[r] += wf.x*c0 + wf.y*c1 + wf.z*c2 + wf.w*c3;
            }
            c0 = n0; c1 = n1; c2 = n2; c3 = n3;
        }
        const float bvv = bv[t];
        #pragma unroll
        for (int r = 0; r < R; r++) sm[OFF_CTX + r * D + t] = acc[r] + bvv;
    }
    __syncthreads();

    // ================= Phase 2b: attn_out -> s_emb (pre-LN1) ==================
    {
        const float* wop = w_out + t;
        float acc[R];
        #pragma unroll
        for (int r = 0; r < R; r++) acc[r] = 0.f;

        float c0 = wop[0*D], c1 = wop[1*D], c2 = wop[2*D], c3 = wop[3*D];
        float n0 = 0.f, n1 = 0.f, n2 = 0.f, n3 = 0.f;
        #pragma unroll 1
        for (int j = 0; j < D; j += 4) {
            if (j + 4 < D) {
                n0 = wop[(j+4)*D]; n1 = wop[(j+5)*D];
                n2 = wop[(j+6)*D]; n3 = wop[(j+7)*D];
            }
            #pragma unroll
            for (int r = 0; r < R; r++) {
                float4 cx = *(const float4*)&sm[OFF_CTX + r * D + j];
                acc[r] += cx.x*c0 + cx.y*c1 + cx.z*c2 + cx.w*c3;
            }
            c0 = n0; c1 = n1; c2 = n2; c3 = n3;
        }
        const float bo = b_out[t];
        #pragma unroll
        for (int r = 0; r < R; r++) sm[OFF_EMB + r * D + t] = acc[r] + bo;
    }
    __syncthreads();

    // ================= Phase 3: LayerNorm1 in place on s_emb ==================
    {
        const int w = t >> 5, lane = t & 31;
        #pragma unroll
        for (int rr = 0; rr < 2; rr++) {
            const int r = w * 2 + rr;
            float x[8]; float s = 0.f;
            #pragma unroll
            for (int i = 0; i < 8; i++) { x[i] = sm[OFF_EMB + r*D + lane + 32*i]; s += x[i]; }
            #pragma unroll
            for (int o = 16; o > 0; o >>= 1) s += __shfl_xor_sync(0xffffffffu, s, o);
            const float mu = s * (1.f / 256.f);
            float v = 0.f;
            #pragma unroll
            for (int i = 0; i < 8; i++) { float dd = x[i] - mu; v += dd * dd; }
            #pragma unroll
            for (int o = 16; o > 0; o >>= 1) v += __shfl_xor_sync(0xffffffffu, v, o);
            const float rstd = rsqrtf(v * (1.f / 256.f) + EPS);
            #pragma unroll
            for (int i = 0; i < 8; i++) {
                const int d0 = lane + 32*i;
                sm[OFF_EMB + r*D + d0] = (x[i] - mu) * rstd * ln1_g[d0] + ln1_b[d0];
            }
        }
    }
    __syncthreads();

    // ========== Phase 4a: hidden[r][f] = relu(emb[r,:] @ w1[:,f] + b1[f]) ======
    {
        float a0[R], a1[R], a2[R];
        #pragma unroll
        for (int r = 0; r < R; r++) { a0[r] = a1[r] = a2[r] = 0.f; }
        const float* w1p = w1 + t;
        float c[12], n[12];
        #pragma unroll
        for (int i = 0; i < 12; i++) n[i] = 0.f;
        #pragma unroll
        for (int kk = 0; kk < 4; kk++) {
            c[kk]     = w1p[kk * F];
            c[4 + kk] = w1p[kk * F + 256];
            c[8 + kk] = w1p[kk * F + 512];
        }
        #pragma unroll 1
        for (int k = 0; k < D; k += 4) {
            if (k + 4 < D) {
                #pragma unroll
                for (int kk = 0; kk < 4; kk++) {
                    n[kk]     = w1p[(k+4+kk) * F];
                    n[4 + kk] = w1p[(k+4+kk) * F + 256];
                    n[8 + kk] = w1p[(k+4+kk) * F + 512];
                }
            }
            #pragma unroll
            for (int r = 0; r < R; r++) {
                float4 e4 = *(const float4*)&sm[OFF_EMB + r * D + k];
                a0[r] += e4.x*c[0] + e4.y*c[1] + e4.z*c[2]  + e4.w*c[3];
                a1[r] += e4.x*c[4] + e4.y*c[5] + e4.z*c[6]  + e4.w*c[7];
                a2[r] += e4.x*c[8] + e4.y*c[9] + e4.z*c[10] + e4.w*c[11];
            }
            #pragma unroll
            for (int i = 0; i < 12; i++) c[i] = n[i];
        }
        const float bb0 = b1[t], bb1 = b1[t + 256], bb2 = b1[t + 512];
        #pragma unroll
        for (int r = 0; r < R; r++) {
            sm[OFF_U + r * F + t]       = fmaxf(a0[r] + bb0, 0.f);
            sm[OFF_U + r * F + t + 256] = fmaxf(a1[r] + bb1, 0.f);
            sm[OFF_U + r * F + t + 512] = fmaxf(a2[r] + bb2, 0.f);
        }
    }
    __syncthreads();

    // ========== Phase 4b: y = emb + hidden @ w2 + b2  (into s_ctx region) =====
    {
        const float* w2p = w2 + t;
        float acc[R];
        #pragma unroll
        for (int r = 0; r < R; r++) acc[r] = 0.f;

        float c0 = w2p[0*D], c1 = w2p[1*D], c2 = w2p[2*D], c3 = w2p[3*D];
        float n0 = 0.f, n1 = 0.f, n2 = 0.f, n3 = 0.f;
        #pragma unroll 1
        for (int f = 0; f < F; f += 4) {
            if (f + 4 < F) {
                n0 = w2p[(f+4)*D]; n1 = w2p[(f+5)*D];
                n2 = w2p[(f+6)*D]; n3 = w2p[(f+7)*D];
            }
            #pragma unroll
            for (int r = 0; r < R; r++) {
                float4 h4 = *(const float4*)&sm[OFF_U + r * F + f];
                acc[r] += h4.x*c0 + h4.y*c1 + h4.z*c2 + h4.w*c3;
            }
            c0 = n0; c1 = n1; c2 = n2; c3 = n3;
        }
        const float bb = b2[t];
        #pragma unroll
        for (int r = 0; r < R; r++)
            sm[OFF_CTX + r * D + t] = sm[OFF_EMB + r * D + t] + acc[r] + bb;
    }
    __syncthreads();

    // ================= Phase 5: LayerNorm2 + store ============================
    {
        const int w = t >> 5, lane = t & 31;
        #pragma unroll
        for (int rr = 0; rr < 2; rr++) {
            const int r = w * 2 + rr;
            float x[8]; float s = 0.f;
            #pragma unroll
            for (int i = 0; i < 8; i++) { x[i] = sm[OFF_CTX + r*D + lane + 32*i]; s += x[i]; }
            #pragma unroll
            for (int o = 16; o > 0; o >>= 1) s += __shfl_xor_sync(0xffffffffu, s, o);
            const float mu = s * (1.f / 256.f);
            float v = 0.f;
            #pragma unroll
            for (int i = 0; i < 8; i++) { float dd = x[i] - mu; v += dd * dd; }
            #pragma unroll
            for (int o = 16; o > 0; o >>= 1) v += __shfl_xor_sync(0xffffffffu, v, o);
            const float rstd = rsqrtf(v * (1.f / 256.f) + EPS);
            const long row = base_row + r;
            if (row < BNS) {
                #pragma unroll
                for (int i = 0; i < 8; i++) {
                    const int d0 = lane + 32*i;
                    out[row * D + d0] = (x[i] - mu) * rstd * ln2_g[d0] + ln2_b[d0];
                }
            }
        }
    }
}

// ============================================================================
// Host entry
// ============================================================================
extern "C" void kernel_launch(void* const* d_in, const int* in_sizes, int n_in,
                              void* d_out, int out_size)
{
    const float* roads  = (const float*)d_in[0];
    const float* seeds  = (const float*)d_in[1];
    const float* w_lin  = (const float*)d_in[2];
    const float* b_lin  = (const float*)d_in[3];
    const float* wq     = (const float*)d_in[4];
    const float* bq     = (const float*)d_in[5];
    const float* wk     = (const float*)d_in[6];
    const float* bk     = (const float*)d_in[7];
    const float* wv     = (const float*)d_in[8];
    const float* bv     = (const float*)d_in[9];
    const float* w_out  = (const float*)d_in[10];
    const float* b_out  = (const float*)d_in[11];
    const float* ln1g   = (const float*)d_in[12];
    const float* ln1b   = (const float*)d_in[13];
    const float* w1     = (const float*)d_in[14];
    const float* b1     = (const float*)d_in[15];
    const float* w2     = (const float*)d_in[16];
    const float* b2     = (const float*)d_in[17];
    const float* ln2g   = (const float*)d_in[18];
    const float* ln2b   = (const float*)d_in[19];
    float* out = (float*)d_out;

    const int BNS = in_sizes[0] / (P * KA);   // 16384 for the bench shapes

    cudaFuncSetAttribute(fused_encoder_kernel,
                         cudaFuncAttributeMaxDynamicSharedMemorySize, SMEM_BYTES);

    precompute_qk_kernel<<<1, NT>>>(seeds, wq, bq, wk, bk);

    const int grid = (BNS + R - 1) / R;
    fused_encoder_kernel<<<grid, NT, SMEM_BYTES>>>(
        roads, w_lin, b_lin, wv, bv, w_out, b_out,
        ln1g, ln1b, w1, b1, w2, b2, ln2g, ln2b, out, BNS);
}